// round 7
// baseline (speedup 1.0000x reference)
#include <cuda_runtime.h>

#define NN   50000
#define EE   800000
#define GG   256
#define HH   128
#define NHID 256
#define NOUT 128

// ---------------- scratch (static device globals; no allocations) ----------------
__device__ float g_bufA[NN * HH];
__device__ float g_bufB[NN * HH];
__device__ int   g_perm[EE];
__device__ int   g_deg[NN];
__device__ int   g_offs[NN + 1];
__device__ int   g_cursor[NN];
__device__ float g_dinv[NN];
__device__ int   g_batch[NN];
__device__ float g_pool[GG * HH];
__device__ float g_cnt[GG];
__device__ float g_hid[GG * NHID];
__device__ int   g_is64;

__device__ __forceinline__ float4 f4zero() { return make_float4(0.f, 0.f, 0.f, 0.f); }
__device__ __forceinline__ float ull_lo(unsigned long long v) { return __uint_as_float((unsigned)v); }
__device__ __forceinline__ float ull_hi(unsigned long long v) { return __uint_as_float((unsigned)(v >> 32)); }

// ---------------- setup: zero buffers + int64/int32 detect (block 0) -------------
__global__ void k_setup(const unsigned int* __restrict__ w) {
    int i = blockIdx.x * blockDim.x + threadIdx.x;
    if (i < NN) g_deg[i] = 0;
    if (i < GG * HH) g_pool[i] = 0.f;
    if (i < GG) g_cnt[i] = 0.f;
    if (blockIdx.x == 0) {
        __shared__ int nz;
        if (threadIdx.x == 0) nz = 0;
        __syncthreads();
        for (int t = threadIdx.x; t < 2048; t += blockDim.x)
            if (w[2 * t + 1] != 0u) nz = 1;   // benign race
        __syncthreads();
        if (threadIdx.x == 0) g_is64 = (nz == 0) ? 1 : 0;
    }
}

// Degree count + batch convert + per-graph node count.
__global__ void k_count(const void* __restrict__ ei, const void* __restrict__ batch) {
    int i = blockIdx.x * blockDim.x + threadIdx.x;
    int is64 = g_is64;
    if (i < EE) {
        int d = is64 ? (int)((const long long*)ei)[EE + i] : ((const int*)ei)[EE + i];
        atomicAdd(&g_deg[d], 1);
    }
    if (i < NN) {
        int b = is64 ? (int)((const long long*)batch)[i] : ((const int*)batch)[i];
        g_batch[i] = b;
        atomicAdd(&g_cnt[b], 1.f);
    }
}

// Single-block scan (serial chunk per thread + one 1024-wide Kogge-Stone) + dinv.
__global__ void k_scan() {
    __shared__ int sh[1024];
    int t = threadIdx.x;
    const int C = (NN + 1023) / 1024;   // 49
    int base = t * C;
    int sum = 0;
    for (int j = 0; j < C; j++) {
        int i = base + j;
        if (i < NN) sum += g_deg[i];
    }
    sh[t] = sum;
    __syncthreads();
    for (int d = 1; d < 1024; d <<= 1) {
        int v = (t >= d) ? sh[t - d] : 0;
        __syncthreads();
        sh[t] += v;
        __syncthreads();
    }
    int run = sh[t] - sum;
    if (t == 0) g_offs[0] = 0;
    for (int j = 0; j < C; j++) {
        int i = base + j;
        if (i < NN) {
            int d = g_deg[i];
            g_cursor[i] = run;
            run += d;
            g_offs[i + 1] = run;
            g_dinv[i] = rsqrtf((float)(d + 1));   // +1 self loop
        }
    }
}

// CSR bucket fill; reads src+dst directly from the original edge_index.
__global__ void k_fill(const void* __restrict__ ei) {
    int i = blockIdx.x * blockDim.x + threadIdx.x;
    if (i < EE) {
        int s, d;
        if (g_is64) {
            const long long* p = (const long long*)ei;
            s = (int)p[i]; d = (int)p[EE + i];
        } else {
            const int* p = (const int*)ei;
            s = p[i]; d = p[EE + i];
        }
        int slot = atomicAdd(&g_cursor[d], 1);
        g_perm[slot] = s;
    }
}

// ============ shared GEMM core: transposed tile xs[k*68+row], 64 rows ============
// 256 threads; warp w owns rows w*8..w*8+7; lane owns cols colg*4..+3.
// Per k: 2 LDS.128 (row-quads, reinterpret as packed row-pairs -> no A MOVs)
//        + 1 LDG.128 W + 4 dup MOVs + 16 FFMA2. fma-pipe dominant.
#define XS_STRIDE 68

__device__ __forceinline__ void gemm_core_store(
    const float* xs, const float* __restrict__ W,
    const float* __restrict__ bias, const float* __restrict__ scale,
    float* __restrict__ C, int M, int m0, int relu, int tid)
{
    int colg = tid & 31;
    int rowg = tid >> 5;

    unsigned long long acc[4][4];   // [row-pair][col]
#pragma unroll
    for (int p = 0; p < 4; p++)
#pragma unroll
        for (int c = 0; c < 4; c++) acc[p][c] = 0ull;

    const float4* W4 = (const float4*)W;
    const float* xb = xs + rowg * 8;

#pragma unroll 4
    for (int k = 0; k < 128; k++) {
        const ulonglong2* xk = (const ulonglong2*)(xb + k * XS_STRIDE);
        ulonglong2 aA = xk[0];     // rows (0,1),(2,3)
        ulonglong2 aB = xk[1];     // rows (4,5),(6,7)
        float4 w4 = __ldg(&W4[k * 32 + colg]);
        unsigned long long pw[4];
        asm("mov.b64 %0, {%1, %1};" : "=l"(pw[0]) : "r"(__float_as_uint(w4.x)));
        asm("mov.b64 %0, {%1, %1};" : "=l"(pw[1]) : "r"(__float_as_uint(w4.y)));
        asm("mov.b64 %0, {%1, %1};" : "=l"(pw[2]) : "r"(__float_as_uint(w4.z)));
        asm("mov.b64 %0, {%1, %1};" : "=l"(pw[3]) : "r"(__float_as_uint(w4.w)));
#pragma unroll
        for (int c = 0; c < 4; c++) {
            asm("fma.rn.f32x2 %0, %1, %2, %0;" : "+l"(acc[0][c]) : "l"(aA.x), "l"(pw[c]));
            asm("fma.rn.f32x2 %0, %1, %2, %0;" : "+l"(acc[1][c]) : "l"(aA.y), "l"(pw[c]));
            asm("fma.rn.f32x2 %0, %1, %2, %0;" : "+l"(acc[2][c]) : "l"(aB.x), "l"(pw[c]));
            asm("fma.rn.f32x2 %0, %1, %2, %0;" : "+l"(acc[3][c]) : "l"(aB.y), "l"(pw[c]));
        }
    }

    float4 bv = f4zero();
    if (bias) bv = ((const float4*)bias)[colg];
    float4* C4 = (float4*)C;
#pragma unroll
    for (int p = 0; p < 4; p++) {
#pragma unroll
        for (int h = 0; h < 2; h++) {
            int grow = m0 + rowg * 8 + 2 * p + h;
            if (grow < M) {
                float s = scale ? scale[grow] : 1.f;
                float4 o;
                o.x = h ? ull_hi(acc[p][0]) : ull_lo(acc[p][0]);
                o.y = h ? ull_hi(acc[p][1]) : ull_lo(acc[p][1]);
                o.z = h ? ull_hi(acc[p][2]) : ull_lo(acc[p][2]);
                o.w = h ? ull_hi(acc[p][3]) : ull_lo(acc[p][3]);
                o.x = fmaf(o.x, s, bv.x); o.y = fmaf(o.y, s, bv.y);
                o.z = fmaf(o.z, s, bv.z); o.w = fmaf(o.w, s, bv.w);
                if (relu) {
                    o.x = fmaxf(o.x, 0.f); o.y = fmaxf(o.y, 0.f);
                    o.z = fmaxf(o.z, 0.f); o.w = fmaxf(o.w, 0.f);
                }
                C4[grow * 32 + colg] = o;
            }
        }
    }
}

// ---------------- standalone GEMM (used for x@W0 with dinv row-scale) ------------
__global__ void __launch_bounds__(256, 3)
k_gemm_t(const float* __restrict__ A, const float* __restrict__ W,
         const float* __restrict__ bias, const float* __restrict__ scale,
         float* __restrict__ C, int M, int relu) {
    __shared__ float xs[128 * XS_STRIDE];
    int tid = threadIdx.x;
    int m0 = blockIdx.x * 64;

    // transposed fill: coalesced LDG.128, scattered STS.32 (minor conflicts)
#pragma unroll
    for (int i = 0; i < 8; i++) {
        int idx = tid + i * 256;               // 2048 float4 slots
        int r = idx >> 5, q = idx & 31;        // row, col-quad
        float4 v = (m0 + r < M) ? ((const float4*)A)[(m0 + r) * 32 + q] : f4zero();
        float* dstp = xs + (4 * q) * XS_STRIDE + r;
        dstp[0] = v.x;
        dstp[XS_STRIDE] = v.y;
        dstp[2 * XS_STRIDE] = v.z;
        dstp[3 * XS_STRIDE] = v.w;
    }
    __syncthreads();
    gemm_core_store(xs, W, bias, scale, C, M, m0, relu, tid);
}

// ---------------- fused GIN agg + GEMM: C = relu((h + sum_nb h) @ W + b) ---------
__global__ void __launch_bounds__(256, 3)
k_agg_gemm(const float* __restrict__ h, const float* __restrict__ W,
           const float* __restrict__ bias, float* __restrict__ C, int M) {
    __shared__ float xs[128 * XS_STRIDE];
    int tid = threadIdx.x;
    int m0 = blockIdx.x * 64;
    int lane = tid & 31;
    int wrp = tid >> 5;
    const float4* h4 = (const float4*)h;

    // gather phase: warp w fills tile rows w*8..w*8+7
#pragma unroll 1
    for (int rr = 0; rr < 8; rr++) {
        int r = wrp * 8 + rr;
        int node = m0 + r;
        float4 acc = f4zero();
        if (node < M) {
            acc = h4[node * 32 + lane];
            int s0 = g_offs[node], s1 = g_offs[node + 1];
            int j = s0;
            for (; j + 3 < s1; j += 4) {
                int n0 = g_perm[j], n1 = g_perm[j + 1], n2 = g_perm[j + 2], n3 = g_perm[j + 3];
                float4 u0 = h4[n0 * 32 + lane];
                float4 u1 = h4[n1 * 32 + lane];
                float4 u2 = h4[n2 * 32 + lane];
                float4 u3 = h4[n3 * 32 + lane];
                acc.x += (u0.x + u1.x) + (u2.x + u3.x);
                acc.y += (u0.y + u1.y) + (u2.y + u3.y);
                acc.z += (u0.z + u1.z) + (u2.z + u3.z);
                acc.w += (u0.w + u1.w) + (u2.w + u3.w);
            }
            for (; j < s1; j++) {
                float4 u = h4[g_perm[j] * 32 + lane];
                acc.x += u.x; acc.y += u.y; acc.z += u.z; acc.w += u.w;
            }
        }
        float* dstp = xs + (4 * lane) * XS_STRIDE + r;
        dstp[0] = acc.x;
        dstp[XS_STRIDE] = acc.y;
        dstp[2 * XS_STRIDE] = acc.z;
        dstp[3 * XS_STRIDE] = acc.w;
    }
    __syncthreads();
    gemm_core_store(xs, W, bias, nullptr, C, M, m0, 1, tid);
}

// ---------------- GCN aggregation (standalone; h pre-scaled by dinv) -------------
// out = relu(b0 + dinv[i]*(h'[i] + sum h'[src]))
__global__ void k_gcn_agg(const float* __restrict__ h, const float* __restrict__ b0,
                          float* __restrict__ out) {
    int node = blockIdx.x * 8 + (threadIdx.x >> 5);
    if (node >= NN) return;
    int lane = threadIdx.x & 31;
    const float4* h4 = (const float4*)h;

    float4 acc = h4[node * 32 + lane];
    int s0 = g_offs[node], s1 = g_offs[node + 1];
    int j = s0;
    for (; j + 3 < s1; j += 4) {
        int n0 = g_perm[j], n1 = g_perm[j + 1], n2 = g_perm[j + 2], n3 = g_perm[j + 3];
        float4 u0 = h4[n0 * 32 + lane];
        float4 u1 = h4[n1 * 32 + lane];
        float4 u2 = h4[n2 * 32 + lane];
        float4 u3 = h4[n3 * 32 + lane];
        acc.x += (u0.x + u1.x) + (u2.x + u3.x);
        acc.y += (u0.y + u1.y) + (u2.y + u3.y);
        acc.z += (u0.z + u1.z) + (u2.z + u3.z);
        acc.w += (u0.w + u1.w) + (u2.w + u3.w);
    }
    for (; j < s1; j++) {
        float4 u = h4[g_perm[j] * 32 + lane];
        acc.x += u.x; acc.y += u.y; acc.z += u.z; acc.w += u.w;
    }
    float di = g_dinv[node];
    float4 b = ((const float4*)b0)[lane];
    float4 o;
    o.x = fmaxf(fmaf(di, acc.x, b.x), 0.f);
    o.y = fmaxf(fmaf(di, acc.y, b.y), 0.f);
    o.z = fmaxf(fmaf(di, acc.z, b.z), 0.f);
    o.w = fmaxf(fmaf(di, acc.w, b.w), 0.f);
    ((float4*)out)[node * 32 + lane] = o;
}

// ---------------- mean pool: sorted batch -> run-accumulate, few atomics ---------
#define POOL_NODES 128
__global__ void k_pool(const float* __restrict__ h) {
    __shared__ int sb[POOL_NODES];
    int c = threadIdx.x;                 // feature column 0..127
    int n0 = blockIdx.x * POOL_NODES;
    int nend = n0 + POOL_NODES; if (nend > NN) nend = NN;
    for (int i = n0 + c; i < nend; i += 128) sb[i - n0] = g_batch[i];
    __syncthreads();

    float acc = 0.f;
    int cur = sb[0];
    for (int n = n0; n < nend; n++) {
        int g = sb[n - n0];
        if (g != cur) {
            atomicAdd(&g_pool[cur * HH + c], acc);
            acc = 0.f; cur = g;
        }
        acc += h[n * HH + c];
    }
    atomicAdd(&g_pool[cur * HH + c], acc);
}

// ---------------- head MLP ----------------
__global__ void k_head1(const float* __restrict__ Wh1, const float* __restrict__ bh1) {
    int g = blockIdx.x, c = threadIdx.x;          // 256 graphs x 256 cols
    float inv = 1.f / fmaxf(g_cnt[g], 1.f);
    float acc = bh1[c];
    const float* pr = &g_pool[g * HH];
#pragma unroll 8
    for (int k = 0; k < HH; k++)
        acc = fmaf(pr[k] * inv, __ldg(&Wh1[k * NHID + c]), acc);
    g_hid[g * NHID + c] = fmaxf(acc, 0.f);
}

__global__ void k_head2(const float* __restrict__ Wh2, const float* __restrict__ bh2,
                        float* __restrict__ out) {
    int g = blockIdx.x, c = threadIdx.x;          // 256 graphs x 128 cols
    float acc = bh2[c];
    const float* hr = &g_hid[g * NHID];
#pragma unroll 8
    for (int k = 0; k < NHID; k++)
        acc = fmaf(hr[k], __ldg(&Wh2[k * NOUT + c]), acc);
    out[g * NOUT + c] = acc;
}

// ---------------- launch ----------------
extern "C" void kernel_launch(void* const* d_in, const int* in_sizes, int n_in,
                              void* d_out, int out_size) {
    (void)in_sizes; (void)n_in; (void)out_size;
    const float* x   = (const float*)d_in[0];
    const void*  ei  = d_in[1];
    const void*  bat = d_in[2];
    const float* W0  = (const float*)d_in[3];
    const float* b0  = (const float*)d_in[4];
    const float* Wg1 = (const float*)d_in[5];
    const float* bg1 = (const float*)d_in[6];
    const float* Wg2 = (const float*)d_in[7];
    const float* bg2 = (const float*)d_in[8];
    const float* Wh1 = (const float*)d_in[9];
    const float* bh1 = (const float*)d_in[10];
    const float* Wh2 = (const float*)d_in[11];
    const float* bh2 = (const float*)d_in[12];
    float* out = (float*)d_out;

    float *bufA, *bufB, *dinv;
    cudaGetSymbolAddress((void**)&bufA, g_bufA);
    cudaGetSymbolAddress((void**)&bufB, g_bufB);
    cudaGetSymbolAddress((void**)&dinv, g_dinv);

    const int TB = 256;
    int gemm_blocks = (NN + 63) / 64;
    int agg_blocks  = (NN + 7) / 8;

    // 0..2: setup
    k_setup<<<(NN + TB - 1) / TB, TB>>>((const unsigned int*)ei);
    k_count<<<(EE + TB - 1) / TB, TB>>>(ei, bat);
    k_scan<<<1, 1024>>>();
    // 3: GCN transform, row-scaled by dinv  (PROFILED LAUNCH)
    k_gemm_t<<<gemm_blocks, 256>>>(x, W0, nullptr, dinv, bufA, NN, 0);
    // 4: CSR bucket fill
    k_fill<<<(EE + TB - 1) / TB, TB>>>(ei);
    // 5: GCN aggregation (+bias+relu) -> h1
    k_gcn_agg<<<agg_blocks, 256>>>(bufA, b0, bufB);
    // 6: GIN layer 1 fused agg+GEMM
    k_agg_gemm<<<gemm_blocks, 256>>>(bufB, Wg1, bg1, bufA, NN);
    // 7: GIN layer 2 fused agg+GEMM
    k_agg_gemm<<<gemm_blocks, 256>>>(bufA, Wg2, bg2, bufB, NN);
    // 8-10: pool + head
    k_pool<<<(NN + POOL_NODES - 1) / POOL_NODES, 128>>>(bufB);
    k_head1<<<GG, NHID>>>(Wh1, bh1);
    k_head2<<<GG, NOUT>>>(Wh2, bh2, out);
}